// round 16
// baseline (speedup 1.0000x reference)
#include <cuda_runtime.h>
#include <cuda_bf16.h>
#include <cuda_fp16.h>
#include <cstdint>

#define LROW 8192
#define NROWS 256
#define OUT_TILE 249
#define NTILES 33   // 33*249 = 8217 >= 8192

// ---------------- device globals ----------------
static __device__ __align__(16) uint32_t g_w2f[10 * 8 * 32 * 2];  // conv2 e4m3 B-frags [kb][nb][lane][2]
static __device__ __align__(16) uint32_t g_w3f[10 * 32 * 2];      // conv3 e4m3 B-frags [kb][lane][2]
static __device__ __align__(16) uint32_t g_w1f[8 * 32 * 2];       // conv1 e4m3 B-frags [nb][lane][2] (K=32 pad, 5 valid)
static __device__ float    g_stat[NROWS * 2];

// ---------------- smem layout (bytes) ----------------
// H rows: 272 x 80B (64 e4m3 + pad). rows 260..271 scratch.
// A1 im2col (272 x 48B = 13056) OVERLAYS the H region (consumed before h1 written).
#define OFF_H    0                    // 21760
#define OFF_W2F  21760                // 20480
#define OFF_W3F  (OFF_W2F + 20480)   // 42240: 2560
#define OFF_W1F  (OFF_W3F + 2560)    // 44800: 2048
#define OFF_PRIM (OFF_W1F + 2048)    // 46848: 264 f32 -> 1056
#define OFF_SY8  (OFF_PRIM + 1056)   // 47904: 288 bytes (264 valid e4m3 + pad)
#define OFF_B1   (OFF_SY8 + 288)     // 48192: 256
#define OFF_B2   (OFF_B1 + 256)      // 48448: 256
#define OFF_B3   (OFF_B2 + 256)      // 48704: 32
#define OFF_COEF (OFF_B3 + 32)       // 48736: 4096
#define OFF_G    (OFF_COEF + 4096)   // 52832: 1024
#define OFF_F    (OFF_G + 1024)      // 53856: 1024
#define SMEM_TOTAL (OFF_F + 1024)    // 54880 (x4 = 219.5 KB/SM)

// ---------------- helpers ----------------
__device__ __forceinline__ uint32_t smem_u32(const void* p) {
    uint32_t a;
    asm("{ .reg .u64 t; cvta.to.shared.u64 t, %1; cvt.u32.u64 %0, t; }" : "=r"(a) : "l"(p));
    return a;
}
__device__ __forceinline__ void sts16(uint32_t a, unsigned short v) {
    asm volatile("st.shared.b16 [%0], %1;" :: "r"(a), "h"(v) : "memory");
}
__device__ __forceinline__ void sts8(uint32_t a, uint32_t v) {
    asm volatile("st.shared.u8 [%0], %1;" :: "r"(a), "r"(v) : "memory");
}
__device__ __forceinline__ void sts128(uint32_t a, uint32_t x, uint32_t y, uint32_t z, uint32_t wv) {
    asm volatile("st.shared.v4.b32 [%0], {%1,%2,%3,%4};" :: "r"(a), "r"(x), "r"(y), "r"(z), "r"(wv) : "memory");
}
__device__ __forceinline__ void cp_async16(uint32_t dst, const void* src) {
    asm volatile("cp.async.cg.shared.global [%0], [%1], 16;" :: "r"(dst), "l"(src) : "memory");
}
__device__ __forceinline__ void ldmatrix_x4(uint32_t* r, uint32_t a) {
    asm volatile("ldmatrix.sync.aligned.m8n8.x4.shared.b16 {%0,%1,%2,%3}, [%4];"
                 : "=r"(r[0]), "=r"(r[1]), "=r"(r[2]), "=r"(r[3]) : "r"(a));
}
__device__ __forceinline__ void mma_fp8_h(uint32_t* d, const uint32_t* a, uint32_t b0, uint32_t b1) {
    asm volatile("mma.sync.aligned.m16n8k32.row.col.f16.e4m3.e4m3.f16 "
                 "{%0,%1}, {%2,%3,%4,%5}, {%6,%7}, {%0,%1};"
                 : "+r"(d[0]), "+r"(d[1])
                 : "r"(a[0]), "r"(a[1]), "r"(a[2]), "r"(a[3]), "r"(b0), "r"(b1));
}
__device__ __forceinline__ unsigned short tanh_h2_e4m3(uint32_t h) {
    asm("tanh.approx.f16x2 %0, %0;" : "+r"(h));
    unsigned short e;
    asm("cvt.rn.satfinite.e4m3x2.f16x2 %0, %1;" : "=h"(e) : "r"(h));
    return e;
}
__device__ __forceinline__ uint32_t packh2(float lo, float hi) {
    uint32_t h;
    asm("cvt.rn.f16x2.f32 %0, %1, %2;" : "=r"(h) : "f"(hi), "f"(lo));
    return h;
}
__device__ __forceinline__ uint32_t pack4_e4m3(float v0, float v1, float v2, float v3) {
    unsigned short lo, hi;
    asm("cvt.rn.satfinite.e4m3x2.f32 %0, %1, %2;" : "=h"(lo) : "f"(v1), "f"(v0));
    asm("cvt.rn.satfinite.e4m3x2.f32 %0, %1, %2;" : "=h"(hi) : "f"(v3), "f"(v2));
    uint32_t r;
    asm("mov.b32 %0, {%1,%2};" : "=r"(r) : "h"(lo), "h"(hi));
    return r;
}
__device__ __forceinline__ uint2 lds64(uint32_t a) {
    uint2 v;
    asm volatile("ld.shared.v2.u32 {%0,%1}, [%2];" : "=r"(v.x), "=r"(v.y) : "r"(a));
    return v;
}
__device__ __forceinline__ uint32_t lds32(uint32_t a) {
    uint32_t v;
    asm volatile("ld.shared.u32 %0, [%1];" : "=r"(v) : "r"(a));
    return v;
}

// ---------------- K0 merged: blocks<256 row stats (1024 thr); blocks>=256 weight packing ----------------
__global__ void k_pre(const float* __restrict__ prim,
                      const float* __restrict__ W1,
                      const float* __restrict__ W2, const float* __restrict__ W3) {
    int tid = threadIdx.x;
    int nthr = blockDim.x;
    if (blockIdx.x < 256) {
        int row = blockIdx.x;
        const float4* p4 = reinterpret_cast<const float4*>(prim + (size_t)row * LROW);
        float mn = 3.4e38f, mx = -3.4e38f;
        for (int i = tid; i < LROW / 4; i += nthr) {
            float4 v = p4[i];
            mn = fminf(mn, fminf(fminf(v.x, v.y), fminf(v.z, v.w)));
            mx = fmaxf(mx, fmaxf(fmaxf(v.x, v.y), fmaxf(v.z, v.w)));
        }
        for (int o = 16; o; o >>= 1) {
            mn = fminf(mn, __shfl_xor_sync(0xffffffffu, mn, o));
            mx = fmaxf(mx, __shfl_xor_sync(0xffffffffu, mx, o));
        }
        __shared__ float smn[32], smx[32];
        if ((tid & 31) == 0) { smn[tid >> 5] = mn; smx[tid >> 5] = mx; }
        __syncthreads();
        if (tid == 0) {
            int nw = nthr >> 5;
            for (int w = 1; w < nw; w++) { mn = fminf(mn, smn[w]); mx = fmaxf(mx, smx[w]); }
            g_stat[2 * row]     = mn;
            g_stat[2 * row + 1] = 1.0f / fmaxf((mx - mn) * 0.5f, 1e-4f);
        }
    } else {
        int base = (blockIdx.x - 256) * nthr + tid;
        int nth = 24 * nthr;
        for (int i = base; i < 10 * 8 * 32 * 2; i += nth) {
            int r = i & 1, lane = (i >> 1) & 31, nb = (i >> 6) & 7, kb = i >> 9;
            int tg = lane & 3, gg = lane >> 2;
            int kshift = kb >> 1;
            int ci = (kb & 1) * 32 + r * 16 + tg * 4;
            int co = nb * 8 + gg;
            const float* wb = W2 + kshift * 4096 + ci * 64 + co;
            g_w2f[i] = pack4_e4m3(wb[0], wb[64], wb[128], wb[192]);
        }
        for (int i = base; i < 10 * 32 * 2; i += nth) {
            int r = i & 1, lane = (i >> 1) & 31, kb = i >> 6;
            int tg = lane & 3, gg = lane >> 2;
            int kshift = kb >> 1;
            int ci = (kb & 1) * 32 + r * 16 + tg * 4;
            float v0 = 0, v1 = 0, v2 = 0, v3 = 0;
            if (gg < 4) {
                const float* wb = W3 + kshift * 256 + ci * 4 + gg;
                v0 = wb[0]; v1 = wb[4]; v2 = wb[8]; v3 = wb[12];
            }
            g_w3f[i] = pack4_e4m3(v0, v1, v2, v3);
        }
        // conv1 B-frags: K index k (0..31, valid k<5), col co
        for (int i = base; i < 8 * 32 * 2; i += nth) {
            int r = i & 1, lane = (i >> 1) & 31, nb = i >> 6;
            int tg = lane & 3, gg = lane >> 2;
            int k0 = r * 16 + tg * 4;
            int co = nb * 8 + gg;
            float v0 = (k0 + 0 < 5) ? W1[(k0 + 0) * 64 + co] : 0.0f;
            float v1 = (k0 + 1 < 5) ? W1[(k0 + 1) * 64 + co] : 0.0f;
            float v2 = (k0 + 2 < 5) ? W1[(k0 + 2) * 64 + co] : 0.0f;
            float v3 = (k0 + 3 < 5) ? W1[(k0 + 3) * 64 + co] : 0.0f;
            g_w1f[i] = pack4_e4m3(v0, v1, v2, v3);
        }
    }
}

// ---------------- mega kernel ----------------
__global__ void __launch_bounds__(256, 4)
k_mega(const float* __restrict__ prim,
       const float* __restrict__ b1g,
       const float* __restrict__ b2g, const float* __restrict__ b3g,
       float* __restrict__ out) {
    extern __shared__ __align__(16) char smem[];
    int tid = threadIdx.x;
    int w = tid >> 5, lane = tid & 31;
    int tg = lane & 3, gg = lane >> 2;
    int row = blockIdx.y;
    int t0 = blockIdx.x * OUT_TILE;
    size_t rb = (size_t)row * LROW;

    uint32_t sb32 = smem_u32(smem);
    uint32_t sh_base = sb32 + OFF_H;
    float* sPrim = reinterpret_cast<float*>(smem + OFF_PRIM);
    float* sb1   = reinterpret_cast<float*>(smem + OFF_B1);
    float* sb2   = reinterpret_cast<float*>(smem + OFF_B2);
    float* sb3   = reinterpret_cast<float*>(smem + OFF_B3);
    float* scoef = reinterpret_cast<float*>(smem + OFF_COEF);
    float* sg    = reinterpret_cast<float*>(smem + OFF_G);
    float* sf    = reinterpret_cast<float*>(smem + OFF_F);

    int m0 = w * 32;

    // ---- phase 0: async weight staging + prim + rescale -> sy8 (e4m3) ----
    {
        const char* w2g = reinterpret_cast<const char*>(g_w2f);
        for (int i = tid; i < 1280; i += 256)
            cp_async16(sb32 + OFF_W2F + i * 16, w2g + (size_t)i * 16);
        const char* w3g = reinterpret_cast<const char*>(g_w3f);
        if (tid < 160)
            cp_async16(sb32 + OFF_W3F + tid * 16, w3g + (size_t)tid * 16);
        const char* w1g = reinterpret_cast<const char*>(g_w1f);
        if (tid < 128)
            cp_async16(sb32 + OFF_W1F + tid * 16, w1g + (size_t)tid * 16);
        asm volatile("cp.async.commit_group;" ::: "memory");

        float mn = g_stat[2 * row], inv = g_stat[2 * row + 1];
        for (int j = tid; j < 264; j += 256) {
            float p = prim[rb + ((t0 - 8 + j) & (LROW - 1))];
            sPrim[j] = p;
            float y = (p - mn) * inv - 1.0f;
            unsigned short e;
            asm("cvt.rn.satfinite.e4m3x2.f32 %0, %1, %2;" : "=h"(e) : "f"(0.0f), "f"(y));
            sts8(sb32 + OFF_SY8 + j, (uint32_t)e);
        }
        if (tid < 64) sb1[tid] = b1g[tid];
        if (tid < 64) sb2[tid] = b2g[tid];
        if (tid < 4)  sb3[tid] = b3g[tid];
    }
    __syncthreads();   // sy8 visible

    // ---- phase 1a: build A1 im2col (272 rows x 32B, stride 48) overlaying H ----
    {
        const uint32_t syb = sb32 + OFF_SY8;
        for (int j = tid; j < 272; j += 256) {
            uint32_t base4 = syb + ((uint32_t)(j >> 2) << 2);
            uint32_t w0 = lds32(base4);
            uint32_t w1v = lds32(base4 + 4);
            uint32_t w2v = lds32(base4 + 8);
            uint32_t s = (j & 3) * 8;
            uint32_t lo = __funnelshift_r(w0, w1v, s);
            uint32_t b4 = __funnelshift_r(w1v, w2v, s) & 0xffu;
            uint32_t a = sh_base + (uint32_t)j * 48;
            sts128(a, lo, b4, 0u, 0u);
            sts128(a + 16, 0u, 0u, 0u, 0u);
        }
    }
    asm volatile("cp.async.wait_group 0;" ::: "memory");
    __syncthreads();   // A1 + weight frags visible

    // ---- phase 1b: conv1 fp8 MMA (M=272, N=64, K=32) + tanh -> sH1 ----
    {
        uint32_t w1p = sb32 + OFF_W1F + lane * 8;
        uint32_t a1Addr = sh_base + (uint32_t)((m0 + (lane & 15)) * 48 + ((lane >> 4) << 4));
        uint32_t accA[2][8][2];
#pragma unroll
        for (int nb = 0; nb < 8; nb++) {
            uint32_t bi = packh2(sb1[nb * 8 + tg * 2], sb1[nb * 8 + tg * 2 + 1]);
            accA[0][nb][0] = bi; accA[0][nb][1] = bi;
            accA[1][nb][0] = bi; accA[1][nb][1] = bi;
        }
        uint32_t af[2][4];
        ldmatrix_x4(af[0], a1Addr);
        ldmatrix_x4(af[1], a1Addr + 768);   // +16 rows * 48
#pragma unroll
        for (int nb = 0; nb < 8; nb++) {
            uint2 b = lds64(w1p + (uint32_t)(nb * 256));
            mma_fp8_h(accA[0][nb], af[0], b.x, b.y);
            mma_fp8_h(accA[1][nb], af[1], b.x, b.y);
        }
        // 17th tile (rows 256..271): this warp handles nb = w
        uint32_t afx[4];
        ldmatrix_x4(afx, sh_base + (uint32_t)((256 + (lane & 15)) * 48 + ((lane >> 4) << 4)));
        uint32_t accX[2];
        {
            uint32_t bi = packh2(sb1[w * 8 + tg * 2], sb1[w * 8 + tg * 2 + 1]);
            accX[0] = bi; accX[1] = bi;
            uint2 b = lds64(w1p + (uint32_t)(w * 256));
            mma_fp8_h(accX, afx, b.x, b.y);
        }
        // tanh now (forces completion of all A1 reads before the barrier)
        unsigned short e1[2][8][2], ex[2];
#pragma unroll
        for (int mt = 0; mt < 2; mt++)
#pragma unroll
            for (int nb = 0; nb < 8; nb++) {
                e1[mt][nb][0] = tanh_h2_e4m3(accA[mt][nb][0]);
                e1[mt][nb][1] = tanh_h2_e4m3(accA[mt][nb][1]);
            }
        ex[0] = tanh_h2_e4m3(accX[0]);
        ex[1] = tanh_h2_e4m3(accX[1]);
        __syncthreads();   // A1 reads done -> safe to overwrite region with sH1
        uint32_t sA = sh_base + (uint32_t)((m0 + gg) * 80 + tg * 2);
#pragma unroll
        for (int mt = 0; mt < 2; mt++)
#pragma unroll
            for (int nb = 0; nb < 8; nb++) {
                sts16(sA + (uint32_t)(mt * 1280 + nb * 8), e1[mt][nb][0]);
                sts16(sA + (uint32_t)(mt * 1280 + 640 + nb * 8), e1[mt][nb][1]);
            }
        sts16(sh_base + (uint32_t)((256 + gg) * 80 + w * 8 + tg * 2), ex[0]);
        sts16(sh_base + (uint32_t)((264 + gg) * 80 + w * 8 + tg * 2), ex[1]);
    }
    __syncthreads();

    // ---- phase 2: conv2 fp8 MMA, f16 accum (M=256, N=64, K=320) ----
    uint32_t aAddr = sh_base + (uint32_t)((m0 + (lane & 15)) * 80 + ((lane >> 4) << 4));
    uint32_t w2p = sb32 + OFF_W2F + lane * 8;
    uint32_t w3p = sb32 + OFF_W3F + lane * 8;

    uint32_t acc[2][8][2];
#pragma unroll
    for (int nb = 0; nb < 8; nb++) {
        uint32_t binit = packh2(sb2[nb * 8 + tg * 2], sb2[nb * 8 + tg * 2 + 1]);
#pragma unroll
        for (int mt = 0; mt < 2; mt++) { acc[mt][nb][0] = binit; acc[mt][nb][1] = binit; }
    }
#pragma unroll
    for (int kb = 0; kb < 10; kb++) {
        uint32_t a[2][4];
        uint32_t ad = aAddr + (uint32_t)((kb >> 1) * 80 + (kb & 1) * 32);
        ldmatrix_x4(a[0], ad);
        ldmatrix_x4(a[1], ad + 1280);
#pragma unroll
        for (int nb = 0; nb < 8; nb++) {
            uint2 b = lds64(w2p + (uint32_t)(((kb * 8 + nb) * 32) * 8));
            mma_fp8_h(acc[0][nb], a[0], b.x, b.y);
            mma_fp8_h(acc[1][nb], a[1], b.x, b.y);
        }
    }

    // ---- phase 3: tanh epilogue -> sH2 (overlay) ----
    unsigned short h2e[2][8][2];
#pragma unroll
    for (int mt = 0; mt < 2; mt++)
#pragma unroll
        for (int nb = 0; nb < 8; nb++) {
            h2e[mt][nb][0] = tanh_h2_e4m3(acc[mt][nb][0]);
            h2e[mt][nb][1] = tanh_h2_e4m3(acc[mt][nb][1]);
        }
    __syncthreads();   // all warps done reading sH1
    {
        uint32_t sAddr = sh_base + (uint32_t)((m0 + gg) * 80 + tg * 2);
#pragma unroll
        for (int mt = 0; mt < 2; mt++)
#pragma unroll
            for (int nb = 0; nb < 8; nb++) {
                sts16(sAddr + (uint32_t)(mt * 1280 + nb * 8), h2e[mt][nb][0]);
                sts16(sAddr + (uint32_t)(mt * 1280 + 640 + nb * 8), h2e[mt][nb][1]);
            }
    }
    __syncthreads();

    // ---- phase 4: conv3 fp8 MMA (M=256, N=8pad, K=320) -> coeffs ----
    uint32_t acc3[2][2];
    {
        uint32_t bz = (tg < 2) ? packh2(sb3[tg * 2], sb3[tg * 2 + 1]) : 0u;
#pragma unroll
        for (int mt = 0; mt < 2; mt++) { acc3[mt][0] = bz; acc3[mt][1] = bz; }
    }
#pragma unroll
    for (int kb = 0; kb < 10; kb++) {
        uint32_t a[2][4];
        uint32_t ad = aAddr + (uint32_t)((kb >> 1) * 80 + (kb & 1) * 32);
        ldmatrix_x4(a[0], ad);
        ldmatrix_x4(a[1], ad + 1280);
        uint2 b = lds64(w3p + (uint32_t)((kb * 32) * 8));
        mma_fp8_h(acc3[0], a[0], b.x, b.y);
        mma_fp8_h(acc3[1], a[1], b.x, b.y);
    }
    if (tg < 2) {
#pragma unroll
        for (int mt = 0; mt < 2; mt++) {
            int p = m0 + mt * 16 + gg;
            int c0 = tg * 2;
            float2 v01 = __half22float2(*reinterpret_cast<__half2*>(&acc3[mt][0]));
            float2 v23 = __half22float2(*reinterpret_cast<__half2*>(&acc3[mt][1]));
            scoef[p * 4 + c0]           = v01.x;
            scoef[p * 4 + c0 + 1]       = v01.y;
            scoef[(p + 8) * 4 + c0]     = v23.x;
            scoef[(p + 8) * 4 + c0 + 1] = v23.y;
        }
    }
    __syncthreads();

    // ---- phase 5: alpha -> grad -> TVD flux -> update ----
    if (tid < 252) {   // grad at position t0-2+tid
        float4 c = *reinterpret_cast<const float4*>(scoef + tid * 4);
        float S = c.x + c.y + c.z + c.w;
        const float NB0 = -0.44721359549995793f;
        const float NBD = -0.13819660112501052f;
        float a0 = (float)( 1.0 / 12.0) + NB0 * S;
        float a1 = (float)(-2.0 / 3.0)  + c.x + NBD * S;
        float a2 =                        c.y + NBD * S;
        float a3 = (float)( 2.0 / 3.0)  + c.z + NBD * S;
        float a4 = (float)(-1.0 / 12.0) + c.w + NBD * S;
        float g = sPrim[tid + 4] * a0 + sPrim[tid + 5] * a1 + sPrim[tid + 6] * a2
                + sPrim[tid + 7] * a3 + sPrim[tid + 8] * a4;
        sg[tid] = g * 64.0f;
    }
    __syncthreads();
    if (tid < 250) {   // flux at position t0-1+tid
        float gm1 = sg[tid], g0 = sg[tid + 1], g1 = sg[tid + 2];
        float aa0 = (g0 < 0.0f) ? -1.0f : 1.0f;
        float ri0 = gm1 / (fmaxf(fabsf(g0), 1e-15f) * aa0);
        float phi0 = (ri0 * ri0 + ri0) / (ri0 * ri0 + 1.0f);
        float aa1 = (g1 < 0.0f) ? -1.0f : 1.0f;
        float ri1 = g0 / (fmaxf(fabsf(g1), 1e-15f) * aa1);
        float phi1 = (ri1 * ri1 + ri1) / (ri1 * ri1 + 1.0f);
        float uL = sPrim[tid + 7] + 0.0078125f * phi0 * g0;
        float uR = sPrim[tid + 8] - 0.0078125f * phi1 * g1;
        sf[tid] = 0.25f * (uL * uL + uR * uR) - 0.25f * fabsf(uL + uR) * (uR - uL);
    }
    __syncthreads();
    if (tid < OUT_TILE) {
        int o = t0 + tid;
        if (o < LROW)
            out[rb + o] = sPrim[tid + 8] - 0.01f * (sf[tid + 1] - sf[tid]);
    }
}

// ---------------- launch ----------------
extern "C" void kernel_launch(void* const* d_in, const int* in_sizes, int n_in,
                              void* d_out, int out_size) {
    const float* Prim = (const float*)d_in[0];
    const float* W1   = (const float*)d_in[1];
    const float* b1   = (const float*)d_in[2];
    const float* W2   = (const float*)d_in[3];
    const float* b2   = (const float*)d_in[4];
    const float* W3   = (const float*)d_in[5];
    const float* b3   = (const float*)d_in[6];
    float* out = (float*)d_out;

    cudaFuncSetAttribute(k_mega, cudaFuncAttributeMaxDynamicSharedMemorySize, SMEM_TOTAL);

    k_pre<<<280, 1024>>>(Prim, W1, W2, W3);
    k_mega<<<dim3(NTILES, NROWS), 256, SMEM_TOTAL>>>(Prim, b1, b2, b3, out);
}